// round 10
// baseline (speedup 1.0000x reference)
#include <cuda_runtime.h>
#include <cstdint>
#include <climits>
#include <cmath>

#define Bn 8
#define Cc 240
#define Nn 16384
#define Rr 32
#define Vv 32768              // R^3
#define K2 480                // 2*C
#define FS 256                // padded row stride of g_featT
#define MAXROWS (Bn * Nn)     // worst case (131072)

// ---------------- scratch (static device globals; no allocations) ----------------
__device__ float g_featT[(size_t)Bn * Nn * FS];   // CSR-ordered point features [slot][256]
__device__ float g_A[(size_t)MAXROWS * K2];       // compact GEMM A (tf32-rounded)
__device__ float g_Y[(size_t)Cc * MAXROWS];       // compact GEMM result, column-major [o][row]
__device__ float g_Wt[Cc * K2];                   // tf32-rounded weights
__device__ int   g_cnt[Bn * Vv];
__device__ int   g_idx[Bn * Nn];                  // packed: idx (15b) | arrival (14b)
__device__ int   g_vox2row[Bn * Vv];              // -1 if empty
__device__ int   g_rowoff[MAXROWS];
__device__ int   g_rowcnt[MAXROWS];
__device__ unsigned long long g_bsum[1024];       // packed (rows<<32)|points per 256-voxel block
__device__ int   g_nrows;
__device__ float g_stats[Bn * 4];

__device__ __forceinline__ float tf32r(float x) {
    uint32_t u;
    asm("cvt.rna.tf32.f32 %0, %1;" : "=r"(u) : "f"(x));
    return __uint_as_float(u);
}

__device__ __forceinline__ void mma_tf32(float* c, const uint32_t* a, const uint32_t* b) {
    asm volatile(
        "mma.sync.aligned.m16n8k8.row.col.f32.tf32.tf32.f32 "
        "{%0,%1,%2,%3}, {%4,%5,%6,%7}, {%8,%9}, {%0,%1,%2,%3};"
        : "+f"(c[0]), "+f"(c[1]), "+f"(c[2]), "+f"(c[3])
        : "r"(a[0]), "r"(a[1]), "r"(a[2]), "r"(a[3]), "r"(b[0]), "r"(b[1]));
}

__device__ __forceinline__ void cpasync16(void* smem_ptr, const void* gptr) {
    unsigned s = (unsigned)__cvta_generic_to_shared(smem_ptr);
    asm volatile("cp.async.cg.shared.global [%0], [%1], 16;" :: "r"(s), "l"(gptr));
}
__device__ __forceinline__ void cp_commit() { asm volatile("cp.async.commit_group;"); }
template <int N>
__device__ __forceinline__ void cp_wait() { asm volatile("cp.async.wait_group %0;" :: "n"(N)); }

// ---------------- 0) fused: zero counters + tf32 W (blocks 0-255) | per-batch stats (256-263) ----
__global__ void __launch_bounds__(1024) init_stats_kernel(const float* __restrict__ W,
                                                          const float* __restrict__ coords) {
    int t = threadIdx.x;
    if (blockIdx.x < 256) {
        int i = blockIdx.x * 1024 + t;                // < B*V
        g_cnt[i] = 0;
        g_vox2row[i] = -1;
        if (i < Cc * K2) g_Wt[i] = tf32r(W[i]);
        return;
    }
    // ---- stats for batch b ----
    int b = blockIdx.x - 256;
    __shared__ float wsm[96];
    __shared__ float smean[3];
    int lane = t & 31, w = t >> 5;
    const float* cx = coords + (size_t)b * 3 * Nn;
    float sx = 0.f, sy = 0.f, sz = 0.f;
    for (int n = t; n < Nn; n += 1024) {
        sx += cx[n];
        sy += cx[Nn + n];
        sz += cx[2 * Nn + n];
    }
#pragma unroll
    for (int d = 16; d; d >>= 1) {
        sx += __shfl_down_sync(0xffffffffu, sx, d);
        sy += __shfl_down_sync(0xffffffffu, sy, d);
        sz += __shfl_down_sync(0xffffffffu, sz, d);
    }
    if (lane == 0) { wsm[w] = sx; wsm[32 + w] = sy; wsm[64 + w] = sz; }
    __syncthreads();
    if (w == 0) {
        float a = wsm[lane], bb = wsm[32 + lane], c = wsm[64 + lane];
#pragma unroll
        for (int d = 16; d; d >>= 1) {
            a += __shfl_down_sync(0xffffffffu, a, d);
            bb += __shfl_down_sync(0xffffffffu, bb, d);
            c += __shfl_down_sync(0xffffffffu, c, d);
        }
        if (lane == 0) {
            smean[0] = a / (float)Nn;
            smean[1] = bb / (float)Nn;
            smean[2] = c / (float)Nn;
        }
    }
    __syncthreads();
    float mx = smean[0], my = smean[1], mz = smean[2];
    float mn = 0.f;
    for (int n = t; n < Nn; n += 1024) {
        float x = cx[n] - mx, y = cx[Nn + n] - my, z = cx[2 * Nn + n] - mz;
        mn = fmaxf(mn, sqrtf(x * x + y * y + z * z));
    }
#pragma unroll
    for (int d = 16; d; d >>= 1) mn = fmaxf(mn, __shfl_down_sync(0xffffffffu, mn, d));
    if (lane == 0) wsm[w] = mn;
    __syncthreads();
    if (w == 0) {
        float a = wsm[lane];
#pragma unroll
        for (int d = 16; d; d >>= 1) a = fmaxf(a, __shfl_down_sync(0xffffffffu, a, d));
        if (lane == 0) {
            g_stats[b * 4 + 0] = mx;
            g_stats[b * 4 + 1] = my;
            g_stats[b * 4 + 2] = mz;
            g_stats[b * 4 + 3] = a * 2.0f;   // denom (EPS = 0)
        }
    }
}

// ---------------- 1) normalized coords + packed voxel idx/arrival + counts ----------------
__global__ void points_kernel(const float* __restrict__ coords, float* __restrict__ nc_out) {
    int i = blockIdx.x * blockDim.x + threadIdx.x;   // < B*N
    int b = i >> 14;
    int n = i & (Nn - 1);
    float mx = g_stats[b * 4 + 0], my = g_stats[b * 4 + 1];
    float mz = g_stats[b * 4 + 2], dn = g_stats[b * 4 + 3];
    const float* cb = coords + (size_t)b * 3 * Nn;
    float x = cb[n], y = cb[Nn + n], z = cb[2 * Nn + n];

    float ncx = ((x - mx) / dn + 0.5f) * (float)Rr;
    float ncy = ((y - my) / dn + 0.5f) * (float)Rr;
    float ncz = ((z - mz) / dn + 0.5f) * (float)Rr;
    ncx = fminf(fmaxf(ncx, 0.f), (float)(Rr - 1));
    ncy = fminf(fmaxf(ncy, 0.f), (float)(Rr - 1));
    ncz = fminf(fmaxf(ncz, 0.f), (float)(Rr - 1));

    float* nb = nc_out + (size_t)b * 3 * Nn;
    nb[n] = ncx;
    nb[Nn + n] = ncy;
    nb[2 * Nn + n] = ncz;

    int vx = (int)rintf(ncx);   // round-half-even == jnp.round
    int vy = (int)rintf(ncy);
    int vz = (int)rintf(ncz);
    int idx = vx * (Rr * Rr) + vy * Rr + vz;
    int arr = atomicAdd(&g_cnt[b * Vv + idx], 1);    // arrival index (order-independent content)
    g_idx[i] = idx | (arr << 15);
}

// ---------------- 2a) block totals (256 voxels/block) ----------------
__global__ void scan1_kernel() {
    int blk = blockIdx.x, t = threadIdx.x;
    int cnt = g_cnt[blk * 256 + t];
    unsigned long long v = ((unsigned long long)(cnt > 0) << 32) | (unsigned)cnt;
#pragma unroll
    for (int d = 16; d; d >>= 1) v += __shfl_down_sync(0xffffffffu, v, d);
    __shared__ unsigned long long w[8];
    if ((t & 31) == 0) w[t >> 5] = v;
    __syncthreads();
    if (t == 0) {
        unsigned long long s = 0;
#pragma unroll
        for (int i = 0; i < 8; ++i) s += w[i];
        g_bsum[blk] = s;
    }
}

// ---------------- 2b) rows+offsets: every block redundantly scans the 1024 bsums ----------------
__global__ void scan3_kernel() {
    int blk = blockIdx.x, t = threadIdx.x, lane = t & 31, w = t >> 5;

    __shared__ unsigned long long part[256];
    {
        const unsigned long long* bs = g_bsum + 4 * t;
        part[t] = bs[0] + bs[1] + bs[2] + bs[3];
    }
    __syncthreads();
    unsigned long long x = part[t];
#pragma unroll
    for (int d = 1; d < 32; d <<= 1) {
        unsigned long long y = __shfl_up_sync(0xffffffffu, x, d);
        if (lane >= d) x += y;
    }
    __shared__ unsigned long long wsum[8];
    if (lane == 31) wsum[w] = x;
    __syncthreads();
    __shared__ unsigned long long wexc[8];
    if (t < 8) {
        unsigned long long s = 0;
        for (int i = 0; i < t; ++i) s += wsum[i];
        wexc[t] = s;
    }
    __syncthreads();
    __shared__ unsigned long long s_base, s_total;
    if (t == (blk >> 2)) {
        unsigned long long excl_chunk = x - part[t] + wexc[w];
        const unsigned long long* bs = g_bsum + (blk & ~3);
        for (int i = 0; i < (blk & 3); ++i) excl_chunk += bs[i];
        s_base = excl_chunk;
    }
    if (t == 255) s_total = x + wexc[7];
    __syncthreads();
    if (blk == 0 && t == 0) g_nrows = (int)(s_total >> 32);

    int bv = blk * 256 + t;
    int cnt = g_cnt[bv];
    unsigned long long v = ((unsigned long long)(cnt > 0) << 32) | (unsigned)cnt;
    unsigned long long orig = v;
#pragma unroll
    for (int d = 1; d < 32; d <<= 1) {
        unsigned long long y = __shfl_up_sync(0xffffffffu, v, d);
        if (lane >= d) v += y;
    }
    __syncthreads();
    if (lane == 31) wsum[w] = v;
    __syncthreads();
    if (t < 8) {
        unsigned long long s = 0;
        for (int i = 0; i < t; ++i) s += wsum[i];
        wexc[t] = s;
    }
    __syncthreads();
    unsigned long long excl = v - orig + wexc[w] + s_base;
    if (cnt > 0) {
        int row = (int)(excl >> 32);
        int off = (int)(excl & 0xffffffffu);
        g_vox2row[bv] = row;
        g_rowcnt[row] = cnt;
        g_rowoff[row] = off;
    }
}

// ---------------- 3) gather-transpose [B][C][N] -> CSR rows, conflict-free write phase --------
// tile 48 ch x 128 pts. Write: t<128 -> point t, ch 0-23; t>=128 -> point t-128, ch 24-47.
// Bank for a load at fixed r: (4*((pq+r)&31)+pk)%32 -> all 32 lanes distinct.
__global__ void __launch_bounds__(256) gtrans_kernel(const float* __restrict__ f) {
    __shared__ float4 sm4[48][32];
    __shared__ int s_slot[128];
    int b = blockIdx.z;
    int n0 = blockIdx.x << 7;
    int c0 = blockIdx.y * 48;
    int t = threadIdx.x;

    if (t < 128) {
        int pk = g_idx[(b << 14) + n0 + t];
        int idx = pk & 0x7fff;
        int row = g_vox2row[b * Vv + idx];
        s_slot[t] = g_rowoff[row] + (pk >> 15);
    }

    int col4 = t & 31, r0 = t >> 5;
#pragma unroll
    for (int rr = 0; rr < 6; ++rr) {
        int r = r0 + rr * 8;
        float4 v = __ldcs(reinterpret_cast<const float4*>(
            f + ((size_t)b * Cc + c0 + r) * Nn + n0 + col4 * 4));
        sm4[r][(col4 + r) & 31] = v;
    }
    __syncthreads();

    const float* smf = reinterpret_cast<const float*>(sm4);
    int p = t & 127, half = t >> 7;
    int pq = p >> 2, pkl = p & 3;
    int cb0 = half * 24;
    float* dst = g_featT + (size_t)s_slot[p] * FS + c0 + cb0;
#pragma unroll
    for (int j = 0; j < 6; ++j) {
        int cb = cb0 + 4 * j;
        float o[4];
#pragma unroll
        for (int kk = 0; kk < 4; ++kk) {
            int r = cb + kk;
            o[kk] = smf[r * 128 + (((pq + r) & 31) << 2) + pkl];
        }
        *reinterpret_cast<float4*>(dst + 4 * j) = make_float4(o[0], o[1], o[2], o[3]);
    }
}

// ---------------- 4) reduce: 4 row-groups per block, CSR rows -> tf32-rounded A ----------------
__global__ void __launch_bounds__(256) reduce_kernel() {
    int nrows = g_nrows;
    int t = threadIdx.x & 63;            // lane within group
    int grpi = threadIdx.x >> 6;         // 0..3
    if (t >= 60) return;
    for (int row = blockIdx.x * 4 + grpi; row < nrows; row += gridDim.x * 4) {
        int cnt = g_rowcnt[row];
        int off = g_rowoff[row];
        const float4* base = reinterpret_cast<const float4*>(
            g_featT + (size_t)off * FS + 4 * t);
        float4 s = make_float4(0.f, 0.f, 0.f, 0.f);
        float4 m = make_float4(-INFINITY, -INFINITY, -INFINITY, -INFINITY);
        for (int p = 0; p < cnt; ++p) {
            float4 v = __ldcs(base + (size_t)p * (FS / 4));
            s.x += v.x; s.y += v.y; s.z += v.z; s.w += v.w;
            m.x = fmaxf(m.x, v.x); m.y = fmaxf(m.y, v.y);
            m.z = fmaxf(m.z, v.z); m.w = fmaxf(m.w, v.w);
        }
        float inv = 1.0f / (float)cnt;
        float* arow = g_A + (size_t)row * K2;
        *reinterpret_cast<float4*>(arow + 4 * t) =
            make_float4(tf32r(m.x), tf32r(m.y), tf32r(m.z), tf32r(m.w));
        *reinterpret_cast<float4*>(arow + Cc + 4 * t) =
            make_float4(tf32r(s.x * inv), tf32r(s.y * inv), tf32r(s.z * inv), tf32r(s.w * inv));
    }
}

// ---------------- 5) tf32 GEMM single-pass N=240, persistent grid -> g_Y[o][row] ----------------
// BM=128, BN=240, BK=32; 384 threads = 12 warps (4M x 3N); warp tile 32x80.
#define AS(s, r, k) As[(((s) * 128 + (r)) * 36) + (k)]
#define BS(s, r, k) Bsm[(((s) * 240 + (r)) * 36) + (k)]
#define GEMM_SMEM ((2 * 128 * 36 + 2 * 240 * 36 + 2 * 240) * 4)
#define GEMM_GRID 296

__global__ void __launch_bounds__(384) gemm_kernel(
    const float* __restrict__ bias,
    const float* __restrict__ gamma,
    const float* __restrict__ beta,
    const float* __restrict__ bmean,
    const float* __restrict__ bvar)
{
    int nrows = g_nrows;
    int ntiles = (nrows + 127) >> 7;

    extern __shared__ float dsm[];
    float* As  = dsm;                       // [2][128][36]
    float* Bsm = dsm + 2 * 128 * 36;        // [2][240][36]
    float* sc_s = Bsm + 2 * 240 * 36;       // [240]
    float* sc_o = sc_s + 240;

    int tid = threadIdx.x;

    if (tid < 240) {
        float s = gamma[tid] * rsqrtf(bvar[tid] + 1e-5f);
        sc_s[tid] = s;
        sc_o[tid] = (bias[tid] - bmean[tid]) * s + beta[tid];
    }

    int lane = tid & 31, warp = tid >> 5;
    int wm = warp & 3, wn = warp >> 2;        // 4 M-warps x 3 N-warps
    int grp = lane >> 2, qk = lane & 3;
    int am = tid >> 1, ah = (tid & 1) * 16;   // A loader (tid < 256)

    for (int tile = blockIdx.x; tile < ntiles; tile += GEMM_GRID) {
        int row0 = tile << 7;

        float acc[2][10][4];
#pragma unroll
        for (int mt = 0; mt < 2; ++mt)
#pragma unroll
            for (int nt = 0; nt < 10; ++nt)
#pragma unroll
                for (int q = 0; q < 4; ++q) acc[mt][nt][q] = 0.f;

        auto load_stage = [&](int kt, int s) {
            int kg = kt * 32;
            if (tid < 256) {
                const float* ap = g_A + (size_t)(row0 + am) * K2 + kg + ah;
#pragma unroll
                for (int i = 0; i < 4; ++i)
                    cpasync16(&AS(s, am, ah + 4 * i), ap + 4 * i);
            }
#pragma unroll
            for (int i = 0; i < 5; ++i) {
                int idx = tid + 384 * i;              // < 1920
                int rowb = idx >> 3;
                int c4 = (idx & 7) << 2;
                cpasync16(&BS(s, rowb, c4), g_Wt + (size_t)rowb * K2 + kg + c4);
            }
            cp_commit();
        };

        __syncthreads();      // protect smem reuse across tiles
        load_stage(0, 0);

        for (int kt = 0; kt < 15; ++kt) {
            int s = kt & 1;
            if (kt < 14) {
                load_stage(kt + 1, s ^ 1);
                cp_wait<1>();
            } else {
                cp_wait<0>();
            }
            __syncthreads();

#pragma unroll
            for (int ks = 0; ks < 4; ++ks) {
                int k8 = ks * 8;
                uint32_t a[2][4], b[10][2];
#pragma unroll
                for (int mt = 0; mt < 2; ++mt) {
                    int r = wm * 32 + mt * 16 + grp;
                    a[mt][0] = __float_as_uint(AS(s, r, k8 + qk));
                    a[mt][1] = __float_as_uint(AS(s, r + 8, k8 + qk));
                    a[mt][2] = __float_as_uint(AS(s, r, k8 + qk + 4));
                    a[mt][3] = __float_as_uint(AS(s, r + 8, k8 + qk + 4));
                }
#pragma unroll
                for (int nt = 0; nt < 10; ++nt) {
                    int nc = wn * 80 + nt * 8 + grp;
                    b[nt][0] = __float_as_uint(BS(s, nc, k8 + qk));
                    b[nt][1] = __float_as_uint(BS(s, nc, k8 + qk + 4));
                }
#pragma unroll
                for (int mt = 0; mt < 2; ++mt)
#pragma unroll
                    for (int nt = 0; nt < 10; ++nt)
                        mma_tf32(acc[mt][nt], a[mt], b[nt]);
            }
            __syncthreads();
        }

        // epilogue: BN + swish -> compact g_Y[o][row]
#pragma unroll
        for (int mt = 0; mt < 2; ++mt) {
            int r0 = row0 + wm * 32 + mt * 16 + grp;
            int r1 = r0 + 8;
            bool v0 = r0 < nrows, v1 = r1 < nrows;
#pragma unroll
            for (int nt = 0; nt < 10; ++nt) {
                int ocl = wn * 80 + nt * 8 + 2 * qk;
#pragma unroll
                for (int h = 0; h < 2; ++h) {
                    int o = ocl + h;
                    float s = sc_s[o], off = sc_o[o];
                    size_t ocol = (size_t)o * MAXROWS;
                    if (v0) {
                        float y = acc[mt][nt][h] * s + off;
                        g_Y[ocol + r0] = y / (1.0f + expf(-y));
                    }
                    if (v1) {
                        float y = acc[mt][nt][2 + h] * s + off;
                        g_Y[ocol + r1] = y / (1.0f + expf(-y));
                    }
                }
            }
        }
    }
}

// ---------------- 6) final output: coalesced merge of g_Y + empty constants ----------------
__global__ void __launch_bounds__(256) write_out_kernel(
    const float* __restrict__ bias,
    const float* __restrict__ gamma,
    const float* __restrict__ beta,
    const float* __restrict__ bmean,
    const float* __restrict__ bvar,
    float* __restrict__ out)          // [B][240][V]
{
    __shared__ float s_empty[60];
    int t = threadIdx.x;
    int span = blockIdx.x;            // < B*V/1024
    int o0 = blockIdx.y * 60;
    int b = span >> 5;                // 32 spans per batch
    int v0 = (span & 31) << 10;

    if (t < 60) {
        int o = o0 + t;
        float s = gamma[o] * rsqrtf(bvar[o] + 1e-5f);
        float y = (bias[o] - bmean[o]) * s + beta[o];
        s_empty[t] = y / (1.0f + expf(-y));
    }
    int4 rows = *reinterpret_cast<const int4*>(g_vox2row + b * Vv + v0 + 4 * t);
    __syncthreads();

    size_t obase = (size_t)b * Cc * Vv + v0 + 4 * t;
    for (int j = 0; j < 60; ++j) {
        int o = o0 + j;
        float e = s_empty[j];
        const float* ycol = g_Y + (size_t)o * MAXROWS;
        float4 r;
        r.x = (rows.x >= 0) ? ycol[rows.x] : e;
        r.y = (rows.y >= 0) ? ycol[rows.y] : e;
        r.z = (rows.z >= 0) ? ycol[rows.z] : e;
        r.w = (rows.w >= 0) ? ycol[rows.w] : e;
        __stcs(reinterpret_cast<float4*>(out + obase + (size_t)o * Vv), r);
    }
}

// ---------------- launch ----------------
extern "C" void kernel_launch(void* const* d_in, const int* in_sizes, int n_in,
                              void* d_out, int out_size) {
    const float* features = (const float*)d_in[0];
    const float* coords   = (const float*)d_in[1];
    const float* conv_w   = (const float*)d_in[2];
    const float* conv_b   = (const float*)d_in[3];
    const float* bn_gamma = (const float*)d_in[4];
    const float* bn_beta  = (const float*)d_in[5];
    const float* bn_mean  = (const float*)d_in[6];
    const float* bn_var   = (const float*)d_in[7];

    float* out = (float*)d_out;                       // [B, C, R^3]
    float* nc_out = out + (size_t)Bn * Cc * Vv;       // [B, 3, N]

    cudaFuncSetAttribute(gemm_kernel, cudaFuncAttributeMaxDynamicSharedMemorySize, GEMM_SMEM);

    init_stats_kernel<<<264, 1024>>>(conv_w, coords);
    points_kernel<<<(Bn * Nn) / 256, 256>>>(coords, nc_out);
    scan1_kernel<<<1024, 256>>>();
    scan3_kernel<<<1024, 256>>>();
    gtrans_kernel<<<dim3(Nn / 128, 5, Bn), 256>>>(features);
    reduce_kernel<<<1024, 256>>>();
    gemm_kernel<<<GEMM_GRID, 384, GEMM_SMEM>>>(conv_b, bn_gamma, bn_beta,
                                               bn_mean, bn_var);
    write_out_kernel<<<dim3((Bn * Vv) / 1024, 4), 256>>>(conv_b, bn_gamma, bn_beta,
                                                         bn_mean, bn_var, out);
}

// round 11
// speedup vs baseline: 1.0836x; 1.0836x over previous
#include <cuda_runtime.h>
#include <cstdint>
#include <climits>
#include <cmath>

#define Bn 8
#define Cc 240
#define Nn 16384
#define Rr 32
#define Vv 32768              // R^3
#define K2 480                // 2*C
#define FS 256                // padded row stride of g_featT
#define MAXROWS (Bn * Nn)     // worst case (131072)

// ---------------- scratch (static device globals; no allocations) ----------------
__device__ float g_featT[(size_t)Bn * Nn * FS];   // CSR-ordered point features [slot][256]
__device__ float g_A[(size_t)MAXROWS * K2];       // compact GEMM A (tf32-rounded)
__device__ float g_Y[(size_t)Cc * MAXROWS];       // compact GEMM result, column-major [o][row]
__device__ float g_Wt[Cc * K2];                   // tf32-rounded weights
__device__ int   g_cnt[Bn * Vv];
__device__ int   g_idx[Bn * Nn];                  // packed: idx (15b) | arrival (14b)
__device__ int   g_vox2row[Bn * Vv];              // -1 if empty
__device__ int   g_rowoff[MAXROWS];
__device__ int   g_rowcnt[MAXROWS];
__device__ unsigned long long g_bsum[1024];       // packed (rows<<32)|points per 256-voxel block
__device__ int   g_nrows;
__device__ float g_stats[Bn * 4];

__device__ __forceinline__ float tf32r(float x) {
    uint32_t u;
    asm("cvt.rna.tf32.f32 %0, %1;" : "=r"(u) : "f"(x));
    return __uint_as_float(u);
}

__device__ __forceinline__ void mma_tf32(float* c, const uint32_t* a, const uint32_t* b) {
    asm volatile(
        "mma.sync.aligned.m16n8k8.row.col.f32.tf32.tf32.f32 "
        "{%0,%1,%2,%3}, {%4,%5,%6,%7}, {%8,%9}, {%0,%1,%2,%3};"
        : "+f"(c[0]), "+f"(c[1]), "+f"(c[2]), "+f"(c[3])
        : "r"(a[0]), "r"(a[1]), "r"(a[2]), "r"(a[3]), "r"(b[0]), "r"(b[1]));
}

__device__ __forceinline__ void cpasync16(void* smem_ptr, const void* gptr) {
    unsigned s = (unsigned)__cvta_generic_to_shared(smem_ptr);
    asm volatile("cp.async.cg.shared.global [%0], [%1], 16;" :: "r"(s), "l"(gptr));
}
__device__ __forceinline__ void cp_commit() { asm volatile("cp.async.commit_group;"); }
template <int N>
__device__ __forceinline__ void cp_wait() { asm volatile("cp.async.wait_group %0;" :: "n"(N)); }

// ---------------- 0) fused: zero counters + tf32 W (blocks 0-255) | per-batch stats (256-263) ----
__global__ void __launch_bounds__(1024) init_stats_kernel(const float* __restrict__ W,
                                                          const float* __restrict__ coords) {
    int t = threadIdx.x;
    if (blockIdx.x < 256) {
        int i = blockIdx.x * 1024 + t;                // < B*V
        g_cnt[i] = 0;
        g_vox2row[i] = -1;
        if (i < Cc * K2) g_Wt[i] = tf32r(W[i]);
        return;
    }
    // ---- stats for batch b ----
    int b = blockIdx.x - 256;
    __shared__ float wsm[96];
    __shared__ float smean[3];
    int lane = t & 31, w = t >> 5;
    const float* cx = coords + (size_t)b * 3 * Nn;
    float sx = 0.f, sy = 0.f, sz = 0.f;
    for (int n = t; n < Nn; n += 1024) {
        sx += cx[n];
        sy += cx[Nn + n];
        sz += cx[2 * Nn + n];
    }
#pragma unroll
    for (int d = 16; d; d >>= 1) {
        sx += __shfl_down_sync(0xffffffffu, sx, d);
        sy += __shfl_down_sync(0xffffffffu, sy, d);
        sz += __shfl_down_sync(0xffffffffu, sz, d);
    }
    if (lane == 0) { wsm[w] = sx; wsm[32 + w] = sy; wsm[64 + w] = sz; }
    __syncthreads();
    if (w == 0) {
        float a = wsm[lane], bb = wsm[32 + lane], c = wsm[64 + lane];
#pragma unroll
        for (int d = 16; d; d >>= 1) {
            a += __shfl_down_sync(0xffffffffu, a, d);
            bb += __shfl_down_sync(0xffffffffu, bb, d);
            c += __shfl_down_sync(0xffffffffu, c, d);
        }
        if (lane == 0) {
            smean[0] = a / (float)Nn;
            smean[1] = bb / (float)Nn;
            smean[2] = c / (float)Nn;
        }
    }
    __syncthreads();
    float mx = smean[0], my = smean[1], mz = smean[2];
    float mn = 0.f;
    for (int n = t; n < Nn; n += 1024) {
        float x = cx[n] - mx, y = cx[Nn + n] - my, z = cx[2 * Nn + n] - mz;
        mn = fmaxf(mn, sqrtf(x * x + y * y + z * z));
    }
#pragma unroll
    for (int d = 16; d; d >>= 1) mn = fmaxf(mn, __shfl_down_sync(0xffffffffu, mn, d));
    if (lane == 0) wsm[w] = mn;
    __syncthreads();
    if (w == 0) {
        float a = wsm[lane];
#pragma unroll
        for (int d = 16; d; d >>= 1) a = fmaxf(a, __shfl_down_sync(0xffffffffu, a, d));
        if (lane == 0) {
            g_stats[b * 4 + 0] = mx;
            g_stats[b * 4 + 1] = my;
            g_stats[b * 4 + 2] = mz;
            g_stats[b * 4 + 3] = a * 2.0f;   // denom (EPS = 0)
        }
    }
}

// ---------------- 1) normalized coords + packed voxel idx/arrival + counts ----------------
__global__ void points_kernel(const float* __restrict__ coords, float* __restrict__ nc_out) {
    int i = blockIdx.x * blockDim.x + threadIdx.x;   // < B*N
    int b = i >> 14;
    int n = i & (Nn - 1);
    float mx = g_stats[b * 4 + 0], my = g_stats[b * 4 + 1];
    float mz = g_stats[b * 4 + 2], dn = g_stats[b * 4 + 3];
    const float* cb = coords + (size_t)b * 3 * Nn;
    float x = cb[n], y = cb[Nn + n], z = cb[2 * Nn + n];

    float ncx = ((x - mx) / dn + 0.5f) * (float)Rr;
    float ncy = ((y - my) / dn + 0.5f) * (float)Rr;
    float ncz = ((z - mz) / dn + 0.5f) * (float)Rr;
    ncx = fminf(fmaxf(ncx, 0.f), (float)(Rr - 1));
    ncy = fminf(fmaxf(ncy, 0.f), (float)(Rr - 1));
    ncz = fminf(fmaxf(ncz, 0.f), (float)(Rr - 1));

    float* nb = nc_out + (size_t)b * 3 * Nn;
    nb[n] = ncx;
    nb[Nn + n] = ncy;
    nb[2 * Nn + n] = ncz;

    int vx = (int)rintf(ncx);   // round-half-even == jnp.round
    int vy = (int)rintf(ncy);
    int vz = (int)rintf(ncz);
    int idx = vx * (Rr * Rr) + vy * Rr + vz;
    int arr = atomicAdd(&g_cnt[b * Vv + idx], 1);    // arrival index (order-independent content)
    g_idx[i] = idx | (arr << 15);
}

// ---------------- 2a) block totals (256 voxels/block) ----------------
__global__ void scan1_kernel() {
    int blk = blockIdx.x, t = threadIdx.x;
    int cnt = g_cnt[blk * 256 + t];
    unsigned long long v = ((unsigned long long)(cnt > 0) << 32) | (unsigned)cnt;
#pragma unroll
    for (int d = 16; d; d >>= 1) v += __shfl_down_sync(0xffffffffu, v, d);
    __shared__ unsigned long long w[8];
    if ((t & 31) == 0) w[t >> 5] = v;
    __syncthreads();
    if (t == 0) {
        unsigned long long s = 0;
#pragma unroll
        for (int i = 0; i < 8; ++i) s += w[i];
        g_bsum[blk] = s;
    }
}

// ---------------- 2b) rows+offsets: every block redundantly scans the 1024 bsums ----------------
__global__ void scan3_kernel() {
    int blk = blockIdx.x, t = threadIdx.x, lane = t & 31, w = t >> 5;

    __shared__ unsigned long long part[256];
    {
        const unsigned long long* bs = g_bsum + 4 * t;
        part[t] = bs[0] + bs[1] + bs[2] + bs[3];
    }
    __syncthreads();
    unsigned long long x = part[t];
#pragma unroll
    for (int d = 1; d < 32; d <<= 1) {
        unsigned long long y = __shfl_up_sync(0xffffffffu, x, d);
        if (lane >= d) x += y;
    }
    __shared__ unsigned long long wsum[8];
    if (lane == 31) wsum[w] = x;
    __syncthreads();
    __shared__ unsigned long long wexc[8];
    if (t < 8) {
        unsigned long long s = 0;
        for (int i = 0; i < t; ++i) s += wsum[i];
        wexc[t] = s;
    }
    __syncthreads();
    __shared__ unsigned long long s_base, s_total;
    if (t == (blk >> 2)) {
        unsigned long long excl_chunk = x - part[t] + wexc[w];
        const unsigned long long* bs = g_bsum + (blk & ~3);
        for (int i = 0; i < (blk & 3); ++i) excl_chunk += bs[i];
        s_base = excl_chunk;
    }
    if (t == 255) s_total = x + wexc[7];
    __syncthreads();
    if (blk == 0 && t == 0) g_nrows = (int)(s_total >> 32);

    int bv = blk * 256 + t;
    int cnt = g_cnt[bv];
    unsigned long long v = ((unsigned long long)(cnt > 0) << 32) | (unsigned)cnt;
    unsigned long long orig = v;
#pragma unroll
    for (int d = 1; d < 32; d <<= 1) {
        unsigned long long y = __shfl_up_sync(0xffffffffu, v, d);
        if (lane >= d) v += y;
    }
    __syncthreads();
    if (lane == 31) wsum[w] = v;
    __syncthreads();
    if (t < 8) {
        unsigned long long s = 0;
        for (int i = 0; i < t; ++i) s += wsum[i];
        wexc[t] = s;
    }
    __syncthreads();
    unsigned long long excl = v - orig + wexc[w] + s_base;
    if (cnt > 0) {
        int row = (int)(excl >> 32);
        int off = (int)(excl & 0xffffffffu);
        g_vox2row[bv] = row;
        g_rowcnt[row] = cnt;
        g_rowoff[row] = off;
    }
}

// ---------------- 3) gather-transpose: coalesced stores + improved smem swizzle --------------
// Placement column for logical (r, pq): (pq + r + (r>>2)) & 31  ->  read-phase conflicts 6->2-way.
__global__ void __launch_bounds__(256) gtrans_kernel(const float* __restrict__ f) {
    __shared__ float4 sm4[48][32];
    __shared__ int s_slot[128];
    int b = blockIdx.z;
    int n0 = blockIdx.x << 7;
    int c0 = blockIdx.y * 48;
    int t = threadIdx.x;

    if (t < 128) {
        int pk = g_idx[(b << 14) + n0 + t];
        int idx = pk & 0x7fff;
        int row = g_vox2row[b * Vv + idx];
        s_slot[t] = g_rowoff[row] + (pk >> 15);
    }

    int col4 = t & 31, r0 = t >> 5;
#pragma unroll
    for (int rr = 0; rr < 6; ++rr) {
        int r = r0 + rr * 8;
        float4 v = __ldcs(reinterpret_cast<const float4*>(
            f + ((size_t)b * Cc + c0 + r) * Nn + n0 + col4 * 4));
        sm4[r][(col4 + r + (r >> 2)) & 31] = v;
    }
    __syncthreads();

    const float* smf = reinterpret_cast<const float*>(sm4);
#pragma unroll
    for (int it = 0; it < 6; ++it) {
        int w = it * 256 + t;
        int j = w % 12;
        int p = w / 12;
        int pq = p >> 2, pk = p & 3;
        float o[4];
#pragma unroll
        for (int kk = 0; kk < 4; ++kk) {
            int r = 4 * j + kk;
            o[kk] = smf[r * 128 + (((pq + r + (r >> 2)) & 31) << 2) + pk];
        }
        *reinterpret_cast<float4*>(g_featT + (size_t)s_slot[p] * FS + c0 + 4 * j) =
            make_float4(o[0], o[1], o[2], o[3]);
    }
}

// ---------------- 4) reduce: 4 row-groups per block, CSR rows -> tf32-rounded A ----------------
__global__ void __launch_bounds__(256) reduce_kernel() {
    int nrows = g_nrows;
    int t = threadIdx.x & 63;            // lane within group
    int grpi = threadIdx.x >> 6;         // 0..3
    if (t >= 60) return;
    for (int row = blockIdx.x * 4 + grpi; row < nrows; row += gridDim.x * 4) {
        int cnt = g_rowcnt[row];
        int off = g_rowoff[row];
        const float4* base = reinterpret_cast<const float4*>(
            g_featT + (size_t)off * FS + 4 * t);
        float4 s = make_float4(0.f, 0.f, 0.f, 0.f);
        float4 m = make_float4(-INFINITY, -INFINITY, -INFINITY, -INFINITY);
        for (int p = 0; p < cnt; ++p) {
            float4 v = __ldcs(base + (size_t)p * (FS / 4));
            s.x += v.x; s.y += v.y; s.z += v.z; s.w += v.w;
            m.x = fmaxf(m.x, v.x); m.y = fmaxf(m.y, v.y);
            m.z = fmaxf(m.z, v.z); m.w = fmaxf(m.w, v.w);
        }
        float inv = 1.0f / (float)cnt;
        float* arow = g_A + (size_t)row * K2;
        *reinterpret_cast<float4*>(arow + 4 * t) =
            make_float4(tf32r(m.x), tf32r(m.y), tf32r(m.z), tf32r(m.w));
        *reinterpret_cast<float4*>(arow + Cc + 4 * t) =
            make_float4(tf32r(s.x * inv), tf32r(s.y * inv), tf32r(s.z * inv), tf32r(s.w * inv));
    }
}

// ---------------- 5) tf32 GEMM single-pass N=240, persistent grid -> g_Y[o][row] ----------------
// BM=128, BN=240, BK=32; 384 threads = 12 warps (4M x 3N); warp tile 32x80.
#define AS(s, r, k) As[(((s) * 128 + (r)) * 36) + (k)]
#define BS(s, r, k) Bsm[(((s) * 240 + (r)) * 36) + (k)]
#define GEMM_SMEM ((2 * 128 * 36 + 2 * 240 * 36 + 2 * 240) * 4)
#define GEMM_GRID 296

__global__ void __launch_bounds__(384) gemm_kernel(
    const float* __restrict__ bias,
    const float* __restrict__ gamma,
    const float* __restrict__ beta,
    const float* __restrict__ bmean,
    const float* __restrict__ bvar)
{
    int nrows = g_nrows;
    int ntiles = (nrows + 127) >> 7;

    extern __shared__ float dsm[];
    float* As  = dsm;                       // [2][128][36]
    float* Bsm = dsm + 2 * 128 * 36;        // [2][240][36]
    float* sc_s = Bsm + 2 * 240 * 36;       // [240]
    float* sc_o = sc_s + 240;

    int tid = threadIdx.x;

    if (tid < 240) {
        float s = gamma[tid] * rsqrtf(bvar[tid] + 1e-5f);
        sc_s[tid] = s;
        sc_o[tid] = (bias[tid] - bmean[tid]) * s + beta[tid];
    }

    int lane = tid & 31, warp = tid >> 5;
    int wm = warp & 3, wn = warp >> 2;        // 4 M-warps x 3 N-warps
    int grp = lane >> 2, qk = lane & 3;
    int am = tid >> 1, ah = (tid & 1) * 16;   // A loader (tid < 256)

    for (int tile = blockIdx.x; tile < ntiles; tile += GEMM_GRID) {
        int row0 = tile << 7;

        float acc[2][10][4];
#pragma unroll
        for (int mt = 0; mt < 2; ++mt)
#pragma unroll
            for (int nt = 0; nt < 10; ++nt)
#pragma unroll
                for (int q = 0; q < 4; ++q) acc[mt][nt][q] = 0.f;

        auto load_stage = [&](int kt, int s) {
            int kg = kt * 32;
            if (tid < 256) {
                const float* ap = g_A + (size_t)(row0 + am) * K2 + kg + ah;
#pragma unroll
                for (int i = 0; i < 4; ++i)
                    cpasync16(&AS(s, am, ah + 4 * i), ap + 4 * i);
            }
#pragma unroll
            for (int i = 0; i < 5; ++i) {
                int idx = tid + 384 * i;              // < 1920
                int rowb = idx >> 3;
                int c4 = (idx & 7) << 2;
                cpasync16(&BS(s, rowb, c4), g_Wt + (size_t)rowb * K2 + kg + c4);
            }
            cp_commit();
        };

        __syncthreads();      // protect smem reuse across tiles
        load_stage(0, 0);

        for (int kt = 0; kt < 15; ++kt) {
            int s = kt & 1;
            if (kt < 14) {
                load_stage(kt + 1, s ^ 1);
                cp_wait<1>();
            } else {
                cp_wait<0>();
            }
            __syncthreads();

#pragma unroll
            for (int ks = 0; ks < 4; ++ks) {
                int k8 = ks * 8;
                uint32_t a[2][4], b[10][2];
#pragma unroll
                for (int mt = 0; mt < 2; ++mt) {
                    int r = wm * 32 + mt * 16 + grp;
                    a[mt][0] = __float_as_uint(AS(s, r, k8 + qk));
                    a[mt][1] = __float_as_uint(AS(s, r + 8, k8 + qk));
                    a[mt][2] = __float_as_uint(AS(s, r, k8 + qk + 4));
                    a[mt][3] = __float_as_uint(AS(s, r + 8, k8 + qk + 4));
                }
#pragma unroll
                for (int nt = 0; nt < 10; ++nt) {
                    int nc = wn * 80 + nt * 8 + grp;
                    b[nt][0] = __float_as_uint(BS(s, nc, k8 + qk));
                    b[nt][1] = __float_as_uint(BS(s, nc, k8 + qk + 4));
                }
#pragma unroll
                for (int mt = 0; mt < 2; ++mt)
#pragma unroll
                    for (int nt = 0; nt < 10; ++nt)
                        mma_tf32(acc[mt][nt], a[mt], b[nt]);
            }
            __syncthreads();
        }

        // epilogue: BN + swish -> compact g_Y[o][row]
#pragma unroll
        for (int mt = 0; mt < 2; ++mt) {
            int r0 = row0 + wm * 32 + mt * 16 + grp;
            int r1 = r0 + 8;
            bool v0 = r0 < nrows, v1 = r1 < nrows;
#pragma unroll
            for (int nt = 0; nt < 10; ++nt) {
                int ocl = wn * 80 + nt * 8 + 2 * qk;
#pragma unroll
                for (int h = 0; h < 2; ++h) {
                    int o = ocl + h;
                    float s = sc_s[o], off = sc_o[o];
                    size_t ocol = (size_t)o * MAXROWS;
                    if (v0) {
                        float y = acc[mt][nt][h] * s + off;
                        g_Y[ocol + r0] = y / (1.0f + expf(-y));
                    }
                    if (v1) {
                        float y = acc[mt][nt][2 + h] * s + off;
                        g_Y[ocol + r1] = y / (1.0f + expf(-y));
                    }
                }
            }
        }
    }
}

// ---------------- 6) final output: coalesced merge of g_Y + empty constants ----------------
__global__ void __launch_bounds__(256) write_out_kernel(
    const float* __restrict__ bias,
    const float* __restrict__ gamma,
    const float* __restrict__ beta,
    const float* __restrict__ bmean,
    const float* __restrict__ bvar,
    float* __restrict__ out)          // [B][240][V]
{
    __shared__ float s_empty[60];
    int t = threadIdx.x;
    int span = blockIdx.x;            // < B*V/1024
    int o0 = blockIdx.y * 60;
    int b = span >> 5;                // 32 spans per batch
    int v0 = (span & 31) << 10;

    if (t < 60) {
        int o = o0 + t;
        float s = gamma[o] * rsqrtf(bvar[o] + 1e-5f);
        float y = (bias[o] - bmean[o]) * s + beta[o];
        s_empty[t] = y / (1.0f + expf(-y));
    }
    int4 rows = *reinterpret_cast<const int4*>(g_vox2row + b * Vv + v0 + 4 * t);
    __syncthreads();

    size_t obase = (size_t)b * Cc * Vv + v0 + 4 * t;
    for (int j = 0; j < 60; ++j) {
        int o = o0 + j;
        float e = s_empty[j];
        const float* ycol = g_Y + (size_t)o * MAXROWS;
        float4 r;
        r.x = (rows.x >= 0) ? ycol[rows.x] : e;
        r.y = (rows.y >= 0) ? ycol[rows.y] : e;
        r.z = (rows.z >= 0) ? ycol[rows.z] : e;
        r.w = (rows.w >= 0) ? ycol[rows.w] : e;
        __stcs(reinterpret_cast<float4*>(out + obase + (size_t)o * Vv), r);
    }
}

// ---------------- launch ----------------
extern "C" void kernel_launch(void* const* d_in, const int* in_sizes, int n_in,
                              void* d_out, int out_size) {
    const float* features = (const float*)d_in[0];
    const float* coords   = (const float*)d_in[1];
    const float* conv_w   = (const float*)d_in[2];
    const float* conv_b   = (const float*)d_in[3];
    const float* bn_gamma = (const float*)d_in[4];
    const float* bn_beta  = (const float*)d_in[5];
    const float* bn_mean  = (const float*)d_in[6];
    const float* bn_var   = (const float*)d_in[7];

    float* out = (float*)d_out;                       // [B, C, R^3]
    float* nc_out = out + (size_t)Bn * Cc * Vv;       // [B, 3, N]

    cudaFuncSetAttribute(gemm_kernel, cudaFuncAttributeMaxDynamicSharedMemorySize, GEMM_SMEM);

    init_stats_kernel<<<264, 1024>>>(conv_w, coords);
    points_kernel<<<(Bn * Nn) / 256, 256>>>(coords, nc_out);
    scan1_kernel<<<1024, 256>>>();
    scan3_kernel<<<1024, 256>>>();
    gtrans_kernel<<<dim3(Nn / 128, 5, Bn), 256>>>(features);
    reduce_kernel<<<1024, 256>>>();
    gemm_kernel<<<GEMM_GRID, 384, GEMM_SMEM>>>(conv_b, bn_gamma, bn_beta,
                                               bn_mean, bn_var);
    write_out_kernel<<<dim3((Bn * Vv) / 1024, 4), 256>>>(conv_b, bn_gamma, bn_beta,
                                                         bn_mean, bn_var, out);
}